// round 6
// baseline (speedup 1.0000x reference)
#include <cuda_runtime.h>
#include <math.h>

#define TT   500
#define BB   256
#define ENCN 700
#define HIDN 128
#define LCAP 128          // max firing enc per (b,t); mean 35, sigma 5.8 -> huge margin
#define NTHD 32768        // BB*HIDN

// ---------------- static device scratch (allocation-free rule) ----------------
__device__ float          g_w1t[ENCN * HIDN];                 // w1 transposed [enc][hid]
__device__ int            g_cnt [BB * TT];                    // firing count per (b,t)
__device__ unsigned short g_list[(size_t)BB * TT * LCAP];     // firing enc indices (ascending)
__device__ float          g_h   [(size_t)TT * BB * HIDN];     // layer-1 pre-filter activations
__device__ unsigned char  g_s1b [(size_t)TT * BB * HIDN];     // layer-1 spikes as bytes
__device__ float          g_o   [TT * BB];                    // layer-2 pre-filter input

// Constants exactly as XLA-on-GPU computes them (bit-exact vs reference — DO NOT TOUCH):
__device__ __forceinline__ void snn_consts(float& d, float& cd1, float& cdr) {
    d        = expf(-0.05f);          // libdevice __nv_expf
    float e1 = expf(1.0f);
    float c1 = __fdiv_rn(e1, 20.0f);
    cd1      = __fmul_rn(c1, d);
    float cr = __fdiv_rn(__fmul_rn(-2.0f, e1), 20.0f);
    cdr      = __fmul_rn(cr, d);
}

// ptxas-contracted scan step (bit-exact vs reference — DO NOT TOUCH):
__device__ __forceinline__ void alpha_step(float d, float cd, float& p, float& q, float in) {
    q = fmaf(d, q, __fmul_rn(cd, p));
    p = fmaf(d, p, in);
}

// ---------------- K_t: transpose w1 [hid][enc] -> [enc][hid] ----------------
__global__ void k_transpose(const float* __restrict__ w1) {
    int i = blockIdx.x * blockDim.x + threadIdx.x;
    if (i < ENCN * HIDN) {
        int e = i >> 7;
        int h = i & (HIDN - 1);
        g_w1t[i] = w1[h * ENCN + e];
    }
}

// ---------------- K0: ballot-compact firing enc indices per (b,t) ----------------
__global__ __launch_bounds__(256) void k_compact(const float* __restrict__ x) {
    int b    = blockIdx.y;
    int t    = blockIdx.x * 8 + (threadIdx.x >> 5);
    int lane = threadIdx.x & 31;
    if (t >= TT) return;

    const float* xr = x + (size_t)b * (TT * ENCN) + (size_t)t * ENCN;

    // issue all 22 loads up front (MLP=22), then serial ballots
    float v[22];
#pragma unroll
    for (int r = 0; r < 22; ++r) {
        int e = r * 32 + lane;
        v[r] = (e < ENCN) ? __ldg(xr + e) : 0.0f;
    }

    size_t lbase = ((size_t)b * TT + t) * LCAP;
    int cnt = 0;
#pragma unroll
    for (int r = 0; r < 22; ++r) {
        bool pred = v[r] > 0.5f;
        unsigned m = __ballot_sync(0xffffffffu, pred);
        if (pred) {
            int pos = cnt + __popc(m & ((1u << lane) - 1u));
            if (pos < LCAP) g_list[lbase + pos] = (unsigned short)(r * 32 + lane);
        }
        cnt += __popc(m);
    }
    if (lane == 0) g_cnt[b * TT + t] = cnt < LCAP ? cnt : LCAP;
}

// ---------------- K_A: sparse gather GEMM ----------------
// grid (B, 4 hid-quarters), 512 thr (16 warps, 2 blocks/SM = 32 warps/SM).
// Warp-per-t striding 16 over all 500 t -> smem fill amortized over ~31 t.
// Whole index list prefetched up-front (6 x LDG.128 = 48 entries); adds are
// predicated to preserve the exact ascending-enc serial order.
__global__ __launch_bounds__(512, 2) void k_gather() {
    extern __shared__ float w1s[];   // [700][32] = 89600 B
    const int b = blockIdx.x, hq = blockIdx.y;
    const int tid  = threadIdx.x;
    const int wid  = tid >> 5;
    const int lane = tid & 31;

    // fill smem with this hid-quarter of w1t (128B coalesced segments)
    for (int i = tid; i < ENCN * 32; i += 512) {
        int e = i >> 5, h = i & 31;
        w1s[i] = g_w1t[e * HIDN + hq * 32 + h];
    }
    __syncthreads();

    for (int t = wid; t < TT; t += 16) {
        int base = b * TT + t;
        int n = __ldg(g_cnt + base);
        const uint4* l4 = (const uint4*)(g_list + (size_t)base * LCAP);

        // prefetch up to 48 indices (covers n<=48; mean 35)
        uint4 v[6];
#pragma unroll
        for (int r = 0; r < 6; ++r)
            v[r] = (8 * r < n) ? __ldg(l4 + r) : make_uint4(0u, 0u, 0u, 0u);

        const int full = (n < 48) ? n : 48;
        float acc = 0.0f;
        int i = 0;
#pragma unroll
        for (int r = 0; r < 6; ++r) {
            unsigned wrd[4] = { v[r].x, v[r].y, v[r].z, v[r].w };
#pragma unroll
            for (int k = 0; k < 4; ++k) {
                int e0 = (int)(wrd[k] & 0xffffu);
                int e1 = (int)(wrd[k] >> 16);
                if (i < full) acc = __fadd_rn(acc, w1s[e0 * 32 + lane]);
                ++i;
                if (i < full) acc = __fadd_rn(acc, w1s[e1 * 32 + lane]);
                ++i;
            }
        }
        // rare tail (P ~ 1%): entries 48..n-1, still ascending order
        const unsigned short* lst = g_list + (size_t)base * LCAP;
        for (int k = 48; k < n; ++k)
            acc = __fadd_rn(acc, w1s[lst[k] * 32 + lane]);

        g_h[(size_t)t * NTHD + b * HIDN + hq * 32 + lane] = acc;
    }
}

// ---------------- K_B: layer-1 filter + spike scan, one thread per (b,h) ----------------
// Spikes stored as bytes (4x less store traffic). (256,1) keeps buffers in regs.
__global__ __launch_bounds__(256, 1) void k_scan1() {
    int gid = blockIdx.x * 256 + threadIdx.x;   // b*128 + h

    float d, cd1, cdr;
    snn_consts(d, cd1, cdr);

    float p1 = 0.f, q1 = 0.f, pr = 0.f, qr = 0.f;
    float bufA[10], bufB[10];

#pragma unroll
    for (int j = 0; j < 10; ++j)
        bufA[j] = __ldg(&g_h[(size_t)j * NTHD + gid]);

    for (int t0 = 0; t0 < TT; t0 += 20) {
#pragma unroll
        for (int j = 0; j < 10; ++j)
            bufB[j] = (t0 + 10 + j < TT) ? __ldg(&g_h[(size_t)(t0 + 10 + j) * NTHD + gid]) : 0.0f;
#pragma unroll
        for (int j = 0; j < 10; ++j) {
            alpha_step(d, cd1, p1, q1, bufA[j]);
            qr = fmaf(d, qr, __fmul_rn(cdr, pr));
            float u = __fadd_rn(q1, qr);
            float s = (u >= 1.0f) ? 1.0f : 0.0f;
            pr = fmaf(d, pr, s);
            g_s1b[(size_t)(t0 + j) * NTHD + gid] = (unsigned char)(u >= 1.0f);
        }
#pragma unroll
        for (int j = 0; j < 10; ++j)
            bufA[j] = (t0 + 20 + j < TT) ? __ldg(&g_h[(size_t)(t0 + 20 + j) * NTHD + gid]) : 0.0f;
#pragma unroll
        for (int j = 0; j < 10; ++j) {
            alpha_step(d, cd1, p1, q1, bufB[j]);
            qr = fmaf(d, qr, __fmul_rn(cdr, pr));
            float u = __fadd_rn(q1, qr);
            float s = (u >= 1.0f) ? 1.0f : 0.0f;
            pr = fmaf(d, pr, s);
            g_s1b[(size_t)(t0 + 10 + j) * NTHD + gid] = (unsigned char)(u >= 1.0f);
        }
    }
}

// ---------------- K_C: o[t,b] = serial ascending-h FFMA over byte spikes ----------------
// fmaf(s,w,acc) with s in {0,1} (exact I2F) is bit-identical to the serial-k GEMV.
__global__ __launch_bounds__(256) void k_dot2(const float* __restrict__ w2) {
    __shared__ float w2s[HIDN];
    if (threadIdx.x < HIDN) w2s[threadIdx.x] = w2[threadIdx.x];
    __syncthreads();

    int t = blockIdx.x;
    int b = threadIdx.x;
    const uint4* sp = (const uint4*)(g_s1b + (size_t)t * NTHD + b * HIDN);

    float acc = 0.0f;
#pragma unroll
    for (int j = 0; j < 8; ++j) {
        uint4 v = __ldg(sp + j);
        unsigned wrd[4] = { v.x, v.y, v.z, v.w };
#pragma unroll
        for (int k = 0; k < 4; ++k) {
            unsigned w = wrd[k];
            int base = j * 16 + k * 4;
            acc = fmaf((float)(w & 0xffu),         w2s[base + 0], acc);
            acc = fmaf((float)((w >> 8) & 0xffu),  w2s[base + 1], acc);
            acc = fmaf((float)((w >> 16) & 0xffu), w2s[base + 2], acc);
            acc = fmaf((float)(w >> 24),           w2s[base + 3], acc);
        }
    }
    g_o[t * BB + b] = acc;
}

// ---------------- K_D: layer-2 filter + spike scan, one thread per b ----------------
__global__ __launch_bounds__(BB, 1) void k_scan2(float* __restrict__ out) {
    int b = threadIdx.x;

    float d, cd1, cdr;
    snn_consts(d, cd1, cdr);

    float p2 = 0.f, q2 = 0.f, pr2 = 0.f, qr2 = 0.f;
    float bufA[10], bufB[10];

#pragma unroll
    for (int j = 0; j < 10; ++j) bufA[j] = g_o[j * BB + b];

    for (int t0 = 0; t0 < TT; t0 += 20) {
#pragma unroll
        for (int j = 0; j < 10; ++j)
            bufB[j] = (t0 + 10 + j < TT) ? g_o[(t0 + 10 + j) * BB + b] : 0.0f;
#pragma unroll
        for (int j = 0; j < 10; ++j) {
            alpha_step(d, cd1, p2, q2, bufA[j]);
            qr2 = fmaf(d, qr2, __fmul_rn(cdr, pr2));
            float u = __fadd_rn(q2, qr2);
            float s = (u >= 1.0f) ? 1.0f : 0.0f;
            pr2 = fmaf(d, pr2, s);
            out[b * TT + (t0 + j)] = s;
        }
#pragma unroll
        for (int j = 0; j < 10; ++j)
            bufA[j] = (t0 + 20 + j < TT) ? g_o[(t0 + 20 + j) * BB + b] : 0.0f;
#pragma unroll
        for (int j = 0; j < 10; ++j) {
            alpha_step(d, cd1, p2, q2, bufB[j]);
            qr2 = fmaf(d, qr2, __fmul_rn(cdr, pr2));
            float u = __fadd_rn(q2, qr2);
            float s = (u >= 1.0f) ? 1.0f : 0.0f;
            pr2 = fmaf(d, pr2, s);
            out[b * TT + (t0 + 10 + j)] = s;
        }
    }
}

// ---------------- launch ----------------
extern "C" void kernel_launch(void* const* d_in, const int* in_sizes, int n_in,
                              void* d_out, int out_size) {
    const float* x = nullptr, *w1 = nullptr, *w2 = nullptr;
    for (int i = 0; i < n_in; ++i) {
        if      (in_sizes[i] == BB * TT * ENCN) x  = (const float*)d_in[i];
        else if (in_sizes[i] == HIDN * ENCN)    w1 = (const float*)d_in[i];
        else if (in_sizes[i] == HIDN)           w2 = (const float*)d_in[i];
    }

    static int smem_set = 0;
    if (!smem_set) {
        cudaFuncSetAttribute(k_gather, cudaFuncAttributeMaxDynamicSharedMemorySize,
                             ENCN * 32 * (int)sizeof(float));
        smem_set = 1;
    }

    k_transpose<<<(ENCN * HIDN + 255) / 256, 256>>>(w1);
    k_compact<<<dim3((TT + 7) / 8, BB), 256>>>(x);
    k_gather<<<dim3(BB, 4), 512, ENCN * 32 * sizeof(float)>>>();
    k_scan1<<<NTHD / 256, 256>>>();
    k_dot2<<<TT, BB>>>(w2);
    k_scan2<<<1, BB>>>((float*)d_out);
}

// round 7
// speedup vs baseline: 1.0527x; 1.0527x over previous
#include <cuda_runtime.h>
#include <math.h>

#define TT   500
#define BB   256
#define ENCN 700
#define HIDN 128
#define LCAP 128          // max firing enc per (b,t); mean 35 -> huge margin
#define NTHD 32768        // BB*HIDN
#define CHB  64           // batch-chunk size (4 chunks pipelined)

// ---------------- static device scratch (allocation-free rule) ----------------
__device__ float          g_w1t[ENCN * HIDN];                 // w1 transposed [enc][hid]
__device__ int            g_cnt [BB * TT];                    // firing count per (b,t)
__device__ unsigned short g_list[(size_t)BB * TT * LCAP];     // firing enc indices (ascending)
__device__ float          g_h   [(size_t)TT * BB * HIDN];     // layer-1 pre-filter activations
__device__ unsigned char  g_s1b [(size_t)TT * BB * HIDN];     // layer-1 spikes as bytes
__device__ float          g_o   [TT * BB];                    // layer-2 pre-filter input

// Constants exactly as XLA-on-GPU computes them (bit-exact — DO NOT TOUCH):
__device__ __forceinline__ void snn_consts(float& d, float& cd1, float& cdr) {
    d        = expf(-0.05f);          // libdevice __nv_expf
    float e1 = expf(1.0f);
    float c1 = __fdiv_rn(e1, 20.0f);
    cd1      = __fmul_rn(c1, d);
    float cr = __fdiv_rn(__fmul_rn(-2.0f, e1), 20.0f);
    cdr      = __fmul_rn(cr, d);
}

// ptxas-contracted scan step (bit-exact — DO NOT TOUCH):
__device__ __forceinline__ void alpha_step(float d, float cd, float& p, float& q, float in) {
    q = fmaf(d, q, __fmul_rn(cd, p));
    p = fmaf(d, p, in);
}

// ---------------- K_t: transpose w1 [hid][enc] -> [enc][hid] ----------------
__global__ void k_transpose(const float* __restrict__ w1) {
    int i = blockIdx.x * blockDim.x + threadIdx.x;
    if (i < ENCN * HIDN) {
        int e = i >> 7;
        int h = i & (HIDN - 1);
        g_w1t[i] = w1[h * ENCN + e];
    }
}

// ---------------- K0: ballot-compact firing enc indices per (b,t) ----------------
// float4 loads: 6 x LDG.128 per warp-row; in-group ordering by (lane, slot) is
// still globally ascending, positions from 4 ballots per 128-element group.
__global__ __launch_bounds__(256) void k_compact(const float* __restrict__ x, int b0) {
    int b    = b0 + blockIdx.y;
    int t    = blockIdx.x * 8 + (threadIdx.x >> 5);
    int lane = threadIdx.x & 31;
    if (t >= TT) return;

    const float4* xr4 = (const float4*)(x + (size_t)b * (TT * ENCN) + (size_t)t * ENCN);

    float4 v[6];
#pragma unroll
    for (int g = 0; g < 6; ++g) {
        int idx = g * 32 + lane;                 // float4 index, 175 per row
        v[g] = (idx < 175) ? __ldg(xr4 + idx)
                           : make_float4(0.f, 0.f, 0.f, 0.f);
    }

    unsigned short* lst = g_list + ((size_t)b * TT + t) * LCAP;
    const unsigned lt = (1u << lane) - 1u;
    int cnt = 0;
#pragma unroll
    for (int g = 0; g < 6; ++g) {
        bool f0 = v[g].x > 0.5f, f1 = v[g].y > 0.5f, f2 = v[g].z > 0.5f, f3 = v[g].w > 0.5f;
        unsigned m0 = __ballot_sync(0xffffffffu, f0);
        unsigned m1 = __ballot_sync(0xffffffffu, f1);
        unsigned m2 = __ballot_sync(0xffffffffu, f2);
        unsigned m3 = __ballot_sync(0xffffffffu, f3);
        int p = cnt + __popc(m0 & lt) + __popc(m1 & lt) + __popc(m2 & lt) + __popc(m3 & lt);
        int e0 = g * 128 + lane * 4;
        if (f0) { if (p < LCAP) lst[p] = (unsigned short)(e0 + 0); ++p; }
        if (f1) { if (p < LCAP) lst[p] = (unsigned short)(e0 + 1); ++p; }
        if (f2) { if (p < LCAP) lst[p] = (unsigned short)(e0 + 2); ++p; }
        if (f3) { if (p < LCAP) lst[p] = (unsigned short)(e0 + 3); ++p; }
        cnt += __popc(m0) + __popc(m1) + __popc(m2) + __popc(m3);
    }
    if (lane == 0) g_cnt[b * TT + t] = cnt < LCAP ? cnt : LCAP;
}

// ---------------- K_A: sparse gather GEMM ----------------
// grid (CHB, 4 hid-quarters), 512 thr, 2 blocks/SM. Warp-per-t stride 16 over 500 t.
// Index list prefetched as uint4; full 8-entry groups run unpredicated (branch, not
// predication, skips empty groups). Ascending-enc serial order preserved exactly.
__global__ __launch_bounds__(512, 2) void k_gather(int b0) {
    extern __shared__ float w1s[];   // [700][32] = 89600 B
    const int b = b0 + blockIdx.x, hq = blockIdx.y;
    const int tid  = threadIdx.x;
    const int wid  = tid >> 5;
    const int lane = tid & 31;

    for (int i = tid; i < ENCN * 32; i += 512) {
        int e = i >> 5, h = i & 31;
        w1s[i] = g_w1t[e * HIDN + hq * 32 + h];
    }
    __syncthreads();

    for (int t = wid; t < TT; t += 16) {
        int base = b * TT + t;
        int n = __ldg(g_cnt + base);
        const uint4* l4 = (const uint4*)(g_list + (size_t)base * LCAP);

        uint4 v[6];
#pragma unroll
        for (int r = 0; r < 6; ++r)
            v[r] = (8 * r < n) ? __ldg(l4 + r) : make_uint4(0u, 0u, 0u, 0u);

        const int nfull = (n < 48 ? n : 48) >> 3;   // full groups of 8
        const int nrem  = (n < 48 ? n : 48) & 7;
        float acc = 0.0f;
#pragma unroll
        for (int r = 0; r < 6; ++r) {
            unsigned wrd[4] = { v[r].x, v[r].y, v[r].z, v[r].w };
            if (r < nfull) {
#pragma unroll
                for (int k = 0; k < 4; ++k) {
                    acc = __fadd_rn(acc, w1s[(int)(wrd[k] & 0xffffu) * 32 + lane]);
                    acc = __fadd_rn(acc, w1s[(int)(wrd[k] >> 16)     * 32 + lane]);
                }
            } else if (r == nfull && nrem) {
#pragma unroll
                for (int k = 0; k < 4; ++k) {
                    if (2 * k     < nrem) acc = __fadd_rn(acc, w1s[(int)(wrd[k] & 0xffffu) * 32 + lane]);
                    if (2 * k + 1 < nrem) acc = __fadd_rn(acc, w1s[(int)(wrd[k] >> 16)     * 32 + lane]);
                }
            }
        }
        // rare tail (P ~ 1%): entries 48..n-1, still ascending
        const unsigned short* lst = g_list + (size_t)base * LCAP;
        for (int k = 48; k < n; ++k)
            acc = __fadd_rn(acc, w1s[lst[k] * 32 + lane]);

        g_h[(size_t)t * NTHD + b * HIDN + hq * 32 + lane] = acc;
    }
}

// ---------------- K_B: layer-1 filter + spike scan, one thread per (b,h) ----------------
__global__ __launch_bounds__(256, 1) void k_scan1(int b0) {
    int gid = b0 * HIDN + blockIdx.x * 256 + threadIdx.x;   // absolute b*128 + h

    float d, cd1, cdr;
    snn_consts(d, cd1, cdr);

    float p1 = 0.f, q1 = 0.f, pr = 0.f, qr = 0.f;
    float bufA[10], bufB[10];

#pragma unroll
    for (int j = 0; j < 10; ++j)
        bufA[j] = __ldg(&g_h[(size_t)j * NTHD + gid]);

    for (int t0 = 0; t0 < TT; t0 += 20) {
#pragma unroll
        for (int j = 0; j < 10; ++j)
            bufB[j] = (t0 + 10 + j < TT) ? __ldg(&g_h[(size_t)(t0 + 10 + j) * NTHD + gid]) : 0.0f;
#pragma unroll
        for (int j = 0; j < 10; ++j) {
            alpha_step(d, cd1, p1, q1, bufA[j]);
            qr = fmaf(d, qr, __fmul_rn(cdr, pr));
            float u = __fadd_rn(q1, qr);
            float s = (u >= 1.0f) ? 1.0f : 0.0f;
            pr = fmaf(d, pr, s);
            g_s1b[(size_t)(t0 + j) * NTHD + gid] = (unsigned char)(u >= 1.0f);
        }
#pragma unroll
        for (int j = 0; j < 10; ++j)
            bufA[j] = (t0 + 20 + j < TT) ? __ldg(&g_h[(size_t)(t0 + 20 + j) * NTHD + gid]) : 0.0f;
#pragma unroll
        for (int j = 0; j < 10; ++j) {
            alpha_step(d, cd1, p1, q1, bufB[j]);
            qr = fmaf(d, qr, __fmul_rn(cdr, pr));
            float u = __fadd_rn(q1, qr);
            float s = (u >= 1.0f) ? 1.0f : 0.0f;
            pr = fmaf(d, pr, s);
            g_s1b[(size_t)(t0 + 10 + j) * NTHD + gid] = (unsigned char)(u >= 1.0f);
        }
    }
}

// ---------------- K_C: o[t,b] = serial ascending-h FFMA over byte spikes ----------------
__global__ __launch_bounds__(256) void k_dot2(const float* __restrict__ w2, int b0) {
    __shared__ float w2s[HIDN];
    if (threadIdx.x < HIDN) w2s[threadIdx.x] = w2[threadIdx.x];
    __syncthreads();

    int idx = blockIdx.x * 256 + threadIdx.x;    // 0 .. TT*CHB-1
    int t = idx >> 6;                            // CHB = 64
    int b = b0 + (idx & 63);
    const uint4* sp = (const uint4*)(g_s1b + (size_t)t * NTHD + b * HIDN);

    float acc = 0.0f;
#pragma unroll
    for (int j = 0; j < 8; ++j) {
        uint4 v = __ldg(sp + j);
        unsigned wrd[4] = { v.x, v.y, v.z, v.w };
#pragma unroll
        for (int k = 0; k < 4; ++k) {
            unsigned w = wrd[k];
            int base = j * 16 + k * 4;
            acc = fmaf((float)(w & 0xffu),         w2s[base + 0], acc);
            acc = fmaf((float)((w >> 8) & 0xffu),  w2s[base + 1], acc);
            acc = fmaf((float)((w >> 16) & 0xffu), w2s[base + 2], acc);
            acc = fmaf((float)(w >> 24),           w2s[base + 3], acc);
        }
    }
    g_o[t * BB + b] = acc;
}

// ---------------- K_D: layer-2 filter + spike scan, one thread per b ----------------
__global__ __launch_bounds__(CHB, 1) void k_scan2(float* __restrict__ out, int b0) {
    int b = b0 + threadIdx.x;

    float d, cd1, cdr;
    snn_consts(d, cd1, cdr);

    float p2 = 0.f, q2 = 0.f, pr2 = 0.f, qr2 = 0.f;
    float bufA[10], bufB[10];

#pragma unroll
    for (int j = 0; j < 10; ++j) bufA[j] = g_o[j * BB + b];

    for (int t0 = 0; t0 < TT; t0 += 20) {
#pragma unroll
        for (int j = 0; j < 10; ++j)
            bufB[j] = (t0 + 10 + j < TT) ? g_o[(t0 + 10 + j) * BB + b] : 0.0f;
#pragma unroll
        for (int j = 0; j < 10; ++j) {
            alpha_step(d, cd1, p2, q2, bufA[j]);
            qr2 = fmaf(d, qr2, __fmul_rn(cdr, pr2));
            float u = __fadd_rn(q2, qr2);
            float s = (u >= 1.0f) ? 1.0f : 0.0f;
            pr2 = fmaf(d, pr2, s);
            out[b * TT + (t0 + j)] = s;
        }
#pragma unroll
        for (int j = 0; j < 10; ++j)
            bufA[j] = (t0 + 20 + j < TT) ? g_o[(t0 + 20 + j) * BB + b] : 0.0f;
#pragma unroll
        for (int j = 0; j < 10; ++j) {
            alpha_step(d, cd1, p2, q2, bufB[j]);
            qr2 = fmaf(d, qr2, __fmul_rn(cdr, pr2));
            float u = __fadd_rn(q2, qr2);
            float s = (u >= 1.0f) ? 1.0f : 0.0f;
            pr2 = fmaf(d, pr2, s);
            out[b * TT + (t0 + 10 + j)] = s;
        }
    }
}

// ---------------- launch: 4-chunk pipeline across 3 forked streams ----------------
extern "C" void kernel_launch(void* const* d_in, const int* in_sizes, int n_in,
                              void* d_out, int out_size) {
    const float* x = nullptr, *w1 = nullptr, *w2 = nullptr;
    for (int i = 0; i < n_in; ++i) {
        if      (in_sizes[i] == BB * TT * ENCN) x  = (const float*)d_in[i];
        else if (in_sizes[i] == HIDN * ENCN)    w1 = (const float*)d_in[i];
        else if (in_sizes[i] == HIDN)           w2 = (const float*)d_in[i];
    }

    static cudaStream_t sC = 0, sG = 0, sS = 0;
    static cudaEvent_t  evFork, evC[4], evG[4], evS[4];
    static int inited = 0;
    if (!inited) {
        cudaFuncSetAttribute(k_gather, cudaFuncAttributeMaxDynamicSharedMemorySize,
                             ENCN * 32 * (int)sizeof(float));
        cudaStreamCreateWithFlags(&sC, cudaStreamNonBlocking);
        cudaStreamCreateWithFlags(&sG, cudaStreamNonBlocking);
        cudaStreamCreateWithFlags(&sS, cudaStreamNonBlocking);
        cudaEventCreateWithFlags(&evFork, cudaEventDisableTiming);
        for (int i = 0; i < 4; ++i) {
            cudaEventCreateWithFlags(&evC[i], cudaEventDisableTiming);
            cudaEventCreateWithFlags(&evG[i], cudaEventDisableTiming);
            cudaEventCreateWithFlags(&evS[i], cudaEventDisableTiming);
        }
        inited = 1;
    }

    // fork the three pipeline streams off the (possibly capturing) origin stream
    cudaEventRecord(evFork, 0);
    cudaStreamWaitEvent(sC, evFork, 0);
    cudaStreamWaitEvent(sG, evFork, 0);
    cudaStreamWaitEvent(sS, evFork, 0);

    k_transpose<<<(ENCN * HIDN + 255) / 256, 256, 0, sG>>>(w1);

    for (int i = 0; i < 4; ++i) {
        int b0 = i * CHB;
        // stage 1: compact (DRAM-bound)
        k_compact<<<dim3((TT + 7) / 8, CHB), 256, 0, sC>>>(x, b0);
        cudaEventRecord(evC[i], sC);
        // stage 2: gather (smem-bound), after this chunk's compact
        cudaStreamWaitEvent(sG, evC[i], 0);
        k_gather<<<dim3(CHB, 4), 512, ENCN * 32 * sizeof(float), sG>>>(b0);
        cudaEventRecord(evG[i], sG);
        // stage 3: scans + GEMV (DRAM/latency-bound)
        cudaStreamWaitEvent(sS, evG[i], 0);
        k_scan1<<<CHB * HIDN / 256, 256, 0, sS>>>(b0);
        k_dot2<<<TT * CHB / 256, 256, 0, sS>>>(w2, b0);
        k_scan2<<<1, CHB, 0, sS>>>((float*)d_out, b0);
        cudaEventRecord(evS[i], sS);
        // join back to origin stream
        cudaStreamWaitEvent(0, evS[i], 0);
    }
}